// round 1
// baseline (speedup 1.0000x reference)
#include <cuda_runtime.h>

// TensorProductLayer: Cartesian tensor product, ell <= 2.
// Per (n,c) pair:
//   out0        = x0*y0 + dot(x1,y1) + frob(x2,y2)
//   out1[d]     = x0*y1[d] + x1[d]*y0 + sum_e x1[e]*y2[e,d] + sum_e x2[d,e]*y1[e]
//   out2[d,e]   = x0*y2[d,e] + x2[d,e]*y0 + x1[d]*y1[e] + sum_f x2[d,f]*y2[f,e]
// HBM-bound: ~2.0 GB total traffic, ~295 us roofline at ~6.8 TB/s.

__global__ void __launch_bounds__(256)
tp_kernel(const float* __restrict__ x0, const float* __restrict__ y0,
          const float* __restrict__ x1, const float* __restrict__ y1,
          const float* __restrict__ x2, const float* __restrict__ y2,
          float* __restrict__ out0, float* __restrict__ out1,
          float* __restrict__ out2, long long NC)
{
    long long i = (long long)blockIdx.x * blockDim.x + threadIdx.x;
    if (i >= NC) return;

    const float a0 = x0[i];
    const float b0 = y0[i];

    float a1[3], b1[3];
#pragma unroll
    for (int d = 0; d < 3; d++) {
        a1[d] = x1[i * 3 + d];
        b1[d] = y1[i * 3 + d];
    }

    float a2[9], b2[9];
#pragma unroll
    for (int d = 0; d < 9; d++) {
        a2[d] = x2[i * 9 + d];
        b2[d] = y2[i * 9 + d];
    }

    // ---- out0 ----
    float o0 = a0 * b0;
#pragma unroll
    for (int d = 0; d < 3; d++) o0 = fmaf(a1[d], b1[d], o0);
#pragma unroll
    for (int d = 0; d < 9; d++) o0 = fmaf(a2[d], b2[d], o0);
    out0[i] = o0;

    // ---- out1 ----
#pragma unroll
    for (int d = 0; d < 3; d++) {
        float o = a0 * b1[d];
        o = fmaf(a1[d], b0, o);
#pragma unroll
        for (int e = 0; e < 3; e++) {
            o = fmaf(a1[e], b2[e * 3 + d], o);   // x1 . y2 (contract first dim of y2)
            o = fmaf(a2[d * 3 + e], b1[e], o);   // x2 . y1 (contract last dim of x2)
        }
        out1[i * 3 + d] = o;
    }

    // ---- out2 ----
#pragma unroll
    for (int d = 0; d < 3; d++) {
#pragma unroll
        for (int e = 0; e < 3; e++) {
            float o = a0 * b2[d * 3 + e];
            o = fmaf(a2[d * 3 + e], b0, o);
            o = fmaf(a1[d], b1[e], o);
#pragma unroll
            for (int f = 0; f < 3; f++)
                o = fmaf(a2[d * 3 + f], b2[f * 3 + e], o);  // x2 @ y2
            out2[i * 9 + d * 3 + e] = o;
        }
    }
}

extern "C" void kernel_launch(void* const* d_in, const int* in_sizes, int n_in,
                              void* d_out, int out_size)
{
    // Robust input classification: the op is NOT symmetric in x<->y, and the
    // harness input order could be dict-order (x0,y0,x1,y1,x2,y2) or
    // signature-order (x0,x1,x2,y0,y1,y2). In BOTH orderings, for each size
    // class the x tensor appears before the y tensor, so classify by element
    // count and take first occurrence = x, second = y.
    long long nc = 0;
    for (int i = 0; i < n_in; i++) {
        long long s = in_sizes[i];
        if (nc == 0 || s < nc) nc = s;
    }

    const float* x0 = nullptr; const float* y0 = nullptr;
    const float* x1 = nullptr; const float* y1 = nullptr;
    const float* x2 = nullptr; const float* y2 = nullptr;

    for (int i = 0; i < n_in; i++) {
        long long s = in_sizes[i];
        const float* p = (const float*)d_in[i];
        if (s == nc)          { if (!x0) x0 = p; else y0 = p; }
        else if (s == 3 * nc) { if (!x1) x1 = p; else y1 = p; }
        else if (s == 9 * nc) { if (!x2) x2 = p; else y2 = p; }
    }

    float* out0 = (float*)d_out;          // nc elements
    float* out1 = out0 + nc;              // 3*nc elements
    float* out2 = out1 + 3 * nc;          // 9*nc elements
    (void)out_size;

    const int threads = 256;
    const long long blocks = (nc + threads - 1) / threads;
    tp_kernel<<<(unsigned)blocks, threads>>>(x0, y0, x1, y1, x2, y2,
                                             out0, out1, out2, nc);
}

// round 3
// speedup vs baseline: 1.3102x; 1.3102x over previous
#include <cuda_runtime.h>

// TensorProductLayer: Cartesian tensor product, ell <= 2.
// Per (n,c) pair:
//   out0        = x0*y0 + dot(x1,y1) + frob(x2,y2)
//   out1[d]     = x0*y1[d] + x1[d]*y0 + sum_e x1[e]*y2[e,d] + sum_e x2[d,e]*y1[e]
//   out2[d,e]   = x0*y2[d,e] + x2[d,e]*y0 + x1[d]*y1[e] + sum_f x2[d,f]*y2[f,e]
//
// R2: smem-staged float4 I/O. All global traffic is coalesced 16B; the
// strided per-pair (stride-3 / stride-9) access happens in smem, which is
// bank-conflict-free (gcd(3,32)=gcd(9,32)=1).

#define TPB 256

__global__ void __launch_bounds__(TPB, 6)
tp_kernel_vec(const float* __restrict__ x0, const float* __restrict__ y0,
              const float* __restrict__ x1, const float* __restrict__ y1,
              const float* __restrict__ x2, const float* __restrict__ y2,
              float* __restrict__ out0, float* __restrict__ out1,
              float* __restrict__ out2)
{
    __shared__ float s1x[TPB * 3], s1y[TPB * 3];
    __shared__ float s2x[TPB * 9], s2y[TPB * 9];

    const int t = threadIdx.x;
    const long long base = (long long)blockIdx.x * TPB;

    // ---- coalesced float4 tile loads ----
    {
        const float4* g1x = (const float4*)(x1 + base * 3);
        const float4* g1y = (const float4*)(y1 + base * 3);
        const float4* g2x = (const float4*)(x2 + base * 9);
        const float4* g2y = (const float4*)(y2 + base * 9);
        if (t < TPB * 3 / 4) {
            ((float4*)s1x)[t] = g1x[t];
            ((float4*)s1y)[t] = g1y[t];
        }
#pragma unroll
        for (int k = t; k < TPB * 9 / 4; k += TPB) {
            ((float4*)s2x)[k] = g2x[k];
            ((float4*)s2y)[k] = g2y[k];
        }
    }

    const float a0 = x0[base + t];
    const float b0 = y0[base + t];
    __syncthreads();

    // ---- gather this pair's operands from smem (conflict-free) ----
    float a1[3], b1[3], a2[9], b2[9];
#pragma unroll
    for (int d = 0; d < 3; d++) {
        a1[d] = s1x[t * 3 + d];
        b1[d] = s1y[t * 3 + d];
    }
#pragma unroll
    for (int d = 0; d < 9; d++) {
        a2[d] = s2x[t * 9 + d];
        b2[d] = s2y[t * 9 + d];
    }
    __syncthreads();   // tiles fully consumed; safe to overwrite with outputs

    // ---- out0 (direct coalesced store) ----
    {
        float o0 = a0 * b0;
#pragma unroll
        for (int d = 0; d < 3; d++) o0 = fmaf(a1[d], b1[d], o0);
#pragma unroll
        for (int d = 0; d < 9; d++) o0 = fmaf(a2[d], b2[d], o0);
        out0[base + t] = o0;
    }

    // ---- out1 -> stage into s1x ----
#pragma unroll
    for (int d = 0; d < 3; d++) {
        float o = a0 * b1[d];
        o = fmaf(a1[d], b0, o);
#pragma unroll
        for (int e = 0; e < 3; e++) {
            o = fmaf(a1[e], b2[e * 3 + d], o);   // x1 . y2 (first dim of y2)
            o = fmaf(a2[d * 3 + e], b1[e], o);   // x2 . y1 (last dim of x2)
        }
        s1x[t * 3 + d] = o;
    }

    // ---- out2 -> stage into s2x ----
#pragma unroll
    for (int d = 0; d < 3; d++) {
#pragma unroll
        for (int e = 0; e < 3; e++) {
            float o = a0 * b2[d * 3 + e];
            o = fmaf(a2[d * 3 + e], b0, o);
            o = fmaf(a1[d], b1[e], o);
#pragma unroll
            for (int f = 0; f < 3; f++)
                o = fmaf(a2[d * 3 + f], b2[f * 3 + e], o);  // x2 @ y2
            s2x[t * 9 + d * 3 + e] = o;
        }
    }
    __syncthreads();

    // ---- coalesced float4 tile stores ----
    {
        float4* g1 = (float4*)(out1 + base * 3);
        float4* g2 = (float4*)(out2 + base * 9);
        if (t < TPB * 3 / 4) g1[t] = ((float4*)s1x)[t];
#pragma unroll
        for (int k = t; k < TPB * 9 / 4; k += TPB) g2[k] = ((float4*)s2x)[k];
    }
}

// Scalar fallback for the (nc % TPB) tail.
__global__ void __launch_bounds__(256)
tp_kernel_tail(const float* __restrict__ x0, const float* __restrict__ y0,
               const float* __restrict__ x1, const float* __restrict__ y1,
               const float* __restrict__ x2, const float* __restrict__ y2,
               float* __restrict__ out0, float* __restrict__ out1,
               float* __restrict__ out2, long long start, long long NC)
{
    long long i = start + (long long)blockIdx.x * blockDim.x + threadIdx.x;
    if (i >= NC) return;

    const float a0 = x0[i];
    const float b0 = y0[i];
    float a1[3], b1[3], a2[9], b2[9];
#pragma unroll
    for (int d = 0; d < 3; d++) { a1[d] = x1[i * 3 + d]; b1[d] = y1[i * 3 + d]; }
#pragma unroll
    for (int d = 0; d < 9; d++) { a2[d] = x2[i * 9 + d]; b2[d] = y2[i * 9 + d]; }

    float o0 = a0 * b0;
#pragma unroll
    for (int d = 0; d < 3; d++) o0 = fmaf(a1[d], b1[d], o0);
#pragma unroll
    for (int d = 0; d < 9; d++) o0 = fmaf(a2[d], b2[d], o0);
    out0[i] = o0;

#pragma unroll
    for (int d = 0; d < 3; d++) {
        float o = a0 * b1[d];
        o = fmaf(a1[d], b0, o);
#pragma unroll
        for (int e = 0; e < 3; e++) {
            o = fmaf(a1[e], b2[e * 3 + d], o);
            o = fmaf(a2[d * 3 + e], b1[e], o);
        }
        out1[i * 3 + d] = o;
    }
#pragma unroll
    for (int d = 0; d < 3; d++)
#pragma unroll
        for (int e = 0; e < 3; e++) {
            float o = a0 * b2[d * 3 + e];
            o = fmaf(a2[d * 3 + e], b0, o);
            o = fmaf(a1[d], b1[e], o);
#pragma unroll
            for (int f = 0; f < 3; f++)
                o = fmaf(a2[d * 3 + f], b2[f * 3 + e], o);
            out2[i * 9 + d * 3 + e] = o;
        }
}

extern "C" void kernel_launch(void* const* d_in, const int* in_sizes, int n_in,
                              void* d_out, int out_size)
{
    // Classify inputs by element count; x precedes y within each size class
    // in both plausible harness orderings.
    long long nc = 0;
    for (int i = 0; i < n_in; i++) {
        long long s = in_sizes[i];
        if (nc == 0 || s < nc) nc = s;
    }

    const float* x0 = nullptr; const float* y0 = nullptr;
    const float* x1 = nullptr; const float* y1 = nullptr;
    const float* x2 = nullptr; const float* y2 = nullptr;
    for (int i = 0; i < n_in; i++) {
        long long s = in_sizes[i];
        const float* p = (const float*)d_in[i];
        if (s == nc)          { if (!x0) x0 = p; else y0 = p; }
        else if (s == 3 * nc) { if (!x1) x1 = p; else y1 = p; }
        else if (s == 9 * nc) { if (!x2) x2 = p; else y2 = p; }
    }

    float* out0 = (float*)d_out;
    float* out1 = out0 + nc;
    float* out2 = out1 + 3 * nc;
    (void)out_size;

    const long long nfull = nc / TPB;      // full 256-pair blocks
    const long long rem   = nc - nfull * TPB;

    if (nfull > 0)
        tp_kernel_vec<<<(unsigned)nfull, TPB>>>(x0, y0, x1, y1, x2, y2,
                                                out0, out1, out2);
    if (rem > 0)
        tp_kernel_tail<<<1, 256>>>(x0, y0, x1, y1, x2, y2,
                                   out0, out1, out2, nfull * TPB, nc);
}